// round 6
// baseline (speedup 1.0000x reference)
#include <cuda_runtime.h>
#include <math.h>

#define NN 10000
#define NE 160000
#define NG 64
#define EMB 128
#define MD 32
#define HID 642
#define EIN 321
#define PLD 644
#define CAT 768
#define EPSF 1e-5f

// ---------------- scratch (static device memory; no allocations) ----------------
__device__ float g_cat[NN * CAT];
__device__ float g_hcat[NN * CAT];
__device__ float g_Pa[NN * PLD];
__device__ float g_Pb[NN * PLD];
__device__ float g_seg[NN * MD];
__device__ float g_cnt[NN];
__device__ float g_z[NN * 160];
__device__ float g_h1[NN * 256];
__device__ float g_h2[NN * 128];
__device__ float g_f1[NN * 256];
__device__ float g_f2[NN * 256];
__device__ float g_f3[NN * 256];
__device__ float g_pool[NG * 256];
__device__ float g_pcnt[NG];

__device__ __forceinline__ float silu_f(float x) {
    return x * __fdividef(1.f, 1.f + __expf(-x));
}

__device__ __forceinline__ float to_tf32(float x) {
    unsigned u;
    asm("cvt.rna.tf32.f32 %0, %1;" : "=r"(u) : "f"(x));
    return __uint_as_float(u);
}

__device__ __forceinline__ void mma_tf32(float* c, unsigned a0, unsigned a1, unsigned a2, unsigned a3,
                                         unsigned b0, unsigned b1) {
    asm volatile(
        "mma.sync.aligned.m16n8k8.row.col.f32.tf32.tf32.f32 "
        "{%0,%1,%2,%3},{%4,%5,%6,%7},{%8,%9},{%0,%1,%2,%3};"
        : "+f"(c[0]), "+f"(c[1]), "+f"(c[2]), "+f"(c[3])
        : "r"(a0), "r"(a1), "r"(a2), "r"(a3), "r"(b0), "r"(b1));
}

// ---------------- small kernels ----------------
__global__ void k_zero_start() {
    int i = blockIdx.x * 256 + threadIdx.x;
    if (i < NN) g_cnt[i] = 0.f;
    if (i < NG * 256) g_pool[i] = 0.f;
    if (i < NG) g_pcnt[i] = 0.f;
    if (i < NN * MD) g_seg[i] = 0.f;
}
__global__ void k_deg(const int* __restrict__ eidx) {
    int e = blockIdx.x * 256 + threadIdx.x;
    if (e < NE) atomicAdd(&g_cnt[eidx[NE + e]], 1.f);
}
__global__ void k_embed(const int* __restrict__ atomids, const float* __restrict__ emb_w) {
    int i = blockIdx.x * 256 + threadIdx.x;
    if (i < NN * EMB) {
        int n = i >> 7, c = i & 127;
        g_cat[n * CAT + c] = emb_w[atomids[n] * EMB + c];
    }
}
__global__ void k_silucat() {
    int i = blockIdx.x * 256 + threadIdx.x;
    if (i < NN * CAT) g_hcat[i] = silu_f(g_cat[i]);
}
__global__ void k_pool(const int* __restrict__ batch) {
    int i = blockIdx.x * 256 + threadIdx.x;
    if (i < NN * 256) {
        int n = i >> 8, c = i & 255;
        atomicAdd(&g_pool[batch[n] * 256 + c], g_f3[i]);
    }
    if (i < NN) atomicAdd(&g_pcnt[batch[i]], 1.f);
}

// ---------------- 3xTF32 tensor-core GEMM v2: M-tile 256, B-frag reuse ----------------
// Tile 256(M) x 64(N), K step 16, 256 threads. Warp w owns rows w*32..w*32+31
// (two m16 row-groups sharing B fragments). 3 mma per tile: hi*hi + hi*lo + lo*hi.
// Requires: K%16==0, N even, lda%4==0, A 16B-aligned, ldc even.
__global__ __launch_bounds__(256) void k_gemm3t(
    const float* __restrict__ A, const float* __restrict__ B,
    const float* __restrict__ bias, float* __restrict__ C,
    int M, int N, int K, int lda, int ldb, int ldc, int act) {
    extern __shared__ float smg[];
    float* sAh = smg;                 // 256 x 20
    float* sAl = smg + 256 * 20;      // 256 x 20
    float* sBh = sAl + 256 * 20;      // 16 x 68
    float* sBl = sBh + 16 * 68;       // 16 x 68
    int tid = threadIdx.x;
    int wid = tid >> 5, lane = tid & 31;
    int g = lane >> 2, tig = lane & 3;
    int r0 = wid << 5;
    int bm = blockIdx.y << 8, bn = blockIdx.x << 6;

    float acc[2][8][4];
#pragma unroll
    for (int p = 0; p < 2; p++)
#pragma unroll
        for (int t = 0; t < 8; t++)
#pragma unroll
            for (int u = 0; u < 4; u++) acc[p][t][u] = 0.f;

    for (int k0 = 0; k0 < K; k0 += 16) {
        __syncthreads();
        // stage A: one row per thread, 16 floats, split hi/lo
        {
            int gr = bm + tid;
            float4 v[4];
#pragma unroll
            for (int q = 0; q < 4; q++) v[q] = make_float4(0.f, 0.f, 0.f, 0.f);
            if (gr < M) {
                const float* ap = A + (size_t)gr * lda + k0;
#pragma unroll
                for (int q = 0; q < 4; q++) v[q] = *(const float4*)(ap + q * 4);
            }
            float* ph = &sAh[tid * 20];
            float* pl = &sAl[tid * 20];
#pragma unroll
            for (int q = 0; q < 4; q++) {
                float h;
                h = to_tf32(v[q].x); ph[q * 4 + 0] = h; pl[q * 4 + 0] = to_tf32(v[q].x - h);
                h = to_tf32(v[q].y); ph[q * 4 + 1] = h; pl[q * 4 + 1] = to_tf32(v[q].y - h);
                h = to_tf32(v[q].z); ph[q * 4 + 2] = h; pl[q * 4 + 2] = to_tf32(v[q].z - h);
                h = to_tf32(v[q].w); ph[q * 4 + 3] = h; pl[q * 4 + 3] = to_tf32(v[q].w - h);
            }
        }
        // stage B tile 16x64
        for (int idx = tid; idx < 16 * 64; idx += 256) {
            int kr = idx >> 6, nc = idx & 63;
            int gc = bn + nc;
            float v = (gc < N) ? B[(size_t)(k0 + kr) * ldb + gc] : 0.f;
            float hcv = to_tf32(v);
            sBh[kr * 68 + nc] = hcv;
            sBl[kr * 68 + nc] = to_tf32(v - hcv);
        }
        __syncthreads();
#pragma unroll
        for (int ks = 0; ks < 2; ks++) {
            int kk = ks << 3;
            unsigned ah[2][4], al[2][4];
#pragma unroll
            for (int p = 0; p < 2; p++) {
                int rr = r0 + (p << 4) + g;
                ah[p][0] = __float_as_uint(sAh[rr * 20 + kk + tig]);
                ah[p][1] = __float_as_uint(sAh[(rr + 8) * 20 + kk + tig]);
                ah[p][2] = __float_as_uint(sAh[rr * 20 + kk + tig + 4]);
                ah[p][3] = __float_as_uint(sAh[(rr + 8) * 20 + kk + tig + 4]);
                al[p][0] = __float_as_uint(sAl[rr * 20 + kk + tig]);
                al[p][1] = __float_as_uint(sAl[(rr + 8) * 20 + kk + tig]);
                al[p][2] = __float_as_uint(sAl[rr * 20 + kk + tig + 4]);
                al[p][3] = __float_as_uint(sAl[(rr + 8) * 20 + kk + tig + 4]);
            }
#pragma unroll
            for (int t = 0; t < 8; t++) {
                unsigned bh0 = __float_as_uint(sBh[(kk + tig) * 68 + (t << 3) + g]);
                unsigned bh1 = __float_as_uint(sBh[(kk + tig + 4) * 68 + (t << 3) + g]);
                unsigned bl0 = __float_as_uint(sBl[(kk + tig) * 68 + (t << 3) + g]);
                unsigned bl1 = __float_as_uint(sBl[(kk + tig + 4) * 68 + (t << 3) + g]);
#pragma unroll
                for (int p = 0; p < 2; p++) {
                    mma_tf32(acc[p][t], ah[p][0], ah[p][1], ah[p][2], ah[p][3], bh0, bh1);
                    mma_tf32(acc[p][t], ah[p][0], ah[p][1], ah[p][2], ah[p][3], bl0, bl1);
                    mma_tf32(acc[p][t], al[p][0], al[p][1], al[p][2], al[p][3], bh0, bh1);
                }
            }
        }
    }

#pragma unroll
    for (int p = 0; p < 2; p++) {
        int row0 = bm + r0 + (p << 4) + g, row1 = row0 + 8;
#pragma unroll
        for (int t = 0; t < 8; t++) {
            int col = bn + (t << 3) + (tig << 1);
            if (col >= N) continue;
            float b0v = bias ? bias[col] : 0.f;
            float b1v = bias ? bias[col + 1] : 0.f;
            float v00 = acc[p][t][0] + b0v, v01 = acc[p][t][1] + b1v;
            float v10 = acc[p][t][2] + b0v, v11 = acc[p][t][3] + b1v;
            if (act) { v00 = silu_f(v00); v01 = silu_f(v01); v10 = silu_f(v10); v11 = silu_f(v11); }
            if (row0 < M) *(float2*)&C[(size_t)row0 * ldc + col] = make_float2(v00, v01);
            if (row1 < M) *(float2*)&C[(size_t)row1 * ldc + col] = make_float2(v10, v11);
        }
    }
}

// ---------------- fused edge kernel v3: tf32 mma + register PQ prefetch ----------------
__global__ __launch_bounds__(256) void k_edge3(
    const int* __restrict__ eidx, const float* __restrict__ coords,
    const float* __restrict__ W1, const float* __restrict__ b1,
    const float* __restrict__ W2, const float* __restrict__ b2,
    const float* __restrict__ eng, const float* __restrict__ enb) {
    extern __shared__ float sm[];
    float* s_fe = sm;                       // 128 x 76
    float* s_H = sm + 128 * 76;             // 128 x 68
    float* s_W1c = s_H + 128 * 68;          // 72 x 68
    float* s_W2c = s_W1c + 72 * 68;         // 64 x 36
    float* s_b1 = s_W2c + 64 * 36;          // 648
    float* s_d2 = s_b1 + 648;               // 128
    int* s_src = (int*)(s_d2 + 128);        // 128
    int* s_dst = s_src + 128;               // 128

    int tid = threadIdx.x;
    int e0 = blockIdx.x << 7;

    if (tid < 128) {
        int e = e0 + tid;
        int s = eidx[e], d = eidx[NE + e];
        s_src[tid] = s; s_dst[tid] = d;
        float dx = coords[3 * s + 0] - coords[3 * d + 0];
        float dy = coords[3 * s + 1] - coords[3 * d + 1];
        float dz = coords[3 * s + 2] - coords[3 * d + 2];
        float d2 = dx * dx + dy * dy + dz * dz;
        s_d2[tid] = d2;
        s_fe[tid * 76 + 64] = to_tf32(d2);
#pragma unroll
        for (int j = 65; j < 72; j++) s_fe[tid * 76 + j] = 0.f;
    }
    for (int i = tid; i < 648; i += 256) s_b1[i] = (i < HID) ? b1[i] : 0.f;
    __syncthreads();
    for (int idx = tid; idx < 128 * 32; idx += 256) {
        int e = idx >> 5, i = idx & 31;
        float xs = s_d2[e] * __int_as_float((127 - i) << 23);
        float sv, cv;
        __sincosf(xs, &sv, &cv);
        s_fe[e * 76 + i] = to_tf32(sv);
        s_fe[e * 76 + 32 + i] = to_tf32(cv);
    }

    int wid = tid >> 5, lane = tid & 31;
    int g = lane >> 2, tig = lane & 3;
    int r0 = wid << 4;
    int rlo = r0 + g, rhi = r0 + g + 8;
    int dlo = s_dst[rlo], dhi = s_dst[rhi];
    int slo = s_src[rlo], shi = s_src[rhi];

    float acc[4][4];
#pragma unroll
    for (int t = 0; t < 4; t++)
#pragma unroll
        for (int u = 0; u < 4; u++) acc[t][u] = 0.f;

    for (int c = 0; c < 11; c++) {
        int cb = c << 6;

        // PQ register prefetch: exactly the fragment elements this thread owns.
        // Issued before syncs so the gather latency overlaps staging + GEMM1.
        float pqlx[8], pqly[8], pqhx[8], pqhy[8];
#pragma unroll
        for (int t = 0; t < 8; t++) {
            int gcol = cb + (t << 3) + (tig << 1);
            float lx = 0.f, ly = 0.f, hx = 0.f, hy = 0.f;
            if (gcol < HID) {
                float2 pa0 = *(const float2*)&g_Pa[(size_t)dlo * PLD + gcol];
                float2 pb0 = *(const float2*)&g_Pb[(size_t)slo * PLD + gcol];
                float2 pa1 = *(const float2*)&g_Pa[(size_t)dhi * PLD + gcol];
                float2 pb1 = *(const float2*)&g_Pb[(size_t)shi * PLD + gcol];
                float bb0 = s_b1[gcol], bb1 = s_b1[gcol + 1];
                lx = pa0.x + pb0.x + bb0; ly = pa0.y + pb0.y + bb1;
                hx = pa1.x + pb1.x + bb0; hy = pa1.y + pb1.y + bb1;
            }
            pqlx[t] = lx; pqly[t] = ly; pqhx[t] = hx; pqhy[t] = hy;
        }

        __syncthreads();  // A: prev chunk's GEMM2 done with s_W2c / s_H
        for (int idx = tid; idx < 72 * 64; idx += 256) {
            int k = idx >> 6, n = idx & 63;
            int gj = cb + n;
            float v = (k < 65 && gj < HID) ? W1[(256 + k) * HID + gj] : 0.f;
            s_W1c[k * 68 + n] = to_tf32(v);
        }
        for (int idx = tid; idx < 64 * 32; idx += 256) {
            int j = idx >> 5, n = idx & 31;
            int gj = cb + j;
            float v = (gj < HID) ? W2[gj * MD + n] : 0.f;
            s_W2c[j * 36 + n] = to_tf32(v);
        }
        __syncthreads();  // B: weights visible

        // GEMM1: c1 = FE @ W1c
        float c1[8][4];
#pragma unroll
        for (int t = 0; t < 8; t++)
#pragma unroll
            for (int u = 0; u < 4; u++) c1[t][u] = 0.f;
#pragma unroll
        for (int ks = 0; ks < 9; ks++) {
            int k0 = ks << 3;
            unsigned a0 = __float_as_uint(s_fe[rlo * 76 + k0 + tig]);
            unsigned a1 = __float_as_uint(s_fe[rhi * 76 + k0 + tig]);
            unsigned a2 = __float_as_uint(s_fe[rlo * 76 + k0 + tig + 4]);
            unsigned a3 = __float_as_uint(s_fe[rhi * 76 + k0 + tig + 4]);
#pragma unroll
            for (int t = 0; t < 8; t++) {
                unsigned b0v = __float_as_uint(s_W1c[(k0 + tig) * 68 + (t << 3) + g]);
                unsigned b1v = __float_as_uint(s_W1c[(k0 + tig + 4) * 68 + (t << 3) + g]);
                mma_tf32(c1[t], a0, a1, a2, a3, b0v, b1v);
            }
        }
        // epilogue: H = tf32(silu(c1 + PQ))  (PQ from registers)
#pragma unroll
        for (int t = 0; t < 8; t++) {
            int col = (t << 3) + (tig << 1);
            int i00 = rlo * 68 + col;
            int i10 = rhi * 68 + col;
            s_H[i00] = to_tf32(silu_f(c1[t][0] + pqlx[t]));
            s_H[i00 + 1] = to_tf32(silu_f(c1[t][1] + pqly[t]));
            s_H[i10] = to_tf32(silu_f(c1[t][2] + pqhx[t]));
            s_H[i10 + 1] = to_tf32(silu_f(c1[t][3] + pqhy[t]));
        }
        __syncthreads();  // C: s_H visible

        // GEMM2: acc += H @ W2c
#pragma unroll
        for (int ks = 0; ks < 8; ks++) {
            int k0 = ks << 3;
            unsigned a0 = __float_as_uint(s_H[rlo * 68 + k0 + tig]);
            unsigned a1 = __float_as_uint(s_H[rhi * 68 + k0 + tig]);
            unsigned a2 = __float_as_uint(s_H[rlo * 68 + k0 + tig + 4]);
            unsigned a3 = __float_as_uint(s_H[rhi * 68 + k0 + tig + 4]);
#pragma unroll
            for (int t = 0; t < 4; t++) {
                unsigned b0v = __float_as_uint(s_W2c[(k0 + tig) * 36 + (t << 3) + g]);
                unsigned b1v = __float_as_uint(s_W2c[(k0 + tig + 4) * 36 + (t << 3) + g]);
                mma_tf32(acc[t], a0, a1, a2, a3, b0v, b1v);
            }
        }
    }

    // message epilogue: silu(+b2), LN32 across quad, atomic segment-sum
    float vlo[8], vhi[8];
    float Slo = 0.f, Shi = 0.f;
#pragma unroll
    for (int t = 0; t < 4; t++) {
        int col = (t << 3) + (tig << 1);
        float v0 = silu_f(acc[t][0] + b2[col]);
        float v1 = silu_f(acc[t][1] + b2[col + 1]);
        float v2 = silu_f(acc[t][2] + b2[col]);
        float v3 = silu_f(acc[t][3] + b2[col + 1]);
        vlo[t * 2] = v0; vlo[t * 2 + 1] = v1;
        vhi[t * 2] = v2; vhi[t * 2 + 1] = v3;
        Slo += v0 + v1; Shi += v2 + v3;
    }
    Slo += __shfl_xor_sync(0xffffffffu, Slo, 1);
    Slo += __shfl_xor_sync(0xffffffffu, Slo, 2);
    Shi += __shfl_xor_sync(0xffffffffu, Shi, 1);
    Shi += __shfl_xor_sync(0xffffffffu, Shi, 2);
    float mlo = Slo * (1.f / 32.f), mhi = Shi * (1.f / 32.f);
    float Vlo = 0.f, Vhi = 0.f;
#pragma unroll
    for (int u = 0; u < 8; u++) {
        float d0 = vlo[u] - mlo; Vlo += d0 * d0;
        float d1 = vhi[u] - mhi; Vhi += d1 * d1;
    }
    Vlo += __shfl_xor_sync(0xffffffffu, Vlo, 1);
    Vlo += __shfl_xor_sync(0xffffffffu, Vlo, 2);
    Vhi += __shfl_xor_sync(0xffffffffu, Vhi, 1);
    Vhi += __shfl_xor_sync(0xffffffffu, Vhi, 2);
    float ilo = rsqrtf(Vlo * (1.f / 32.f) + EPSF);
    float ihi = rsqrtf(Vhi * (1.f / 32.f) + EPSF);
#pragma unroll
    for (int t = 0; t < 4; t++) {
#pragma unroll
        for (int d = 0; d < 2; d++) {
            int col = (t << 3) + (tig << 1) + d;
            atomicAdd(&g_seg[dlo * MD + col], (vlo[t * 2 + d] - mlo) * ilo * eng[col] + enb[col]);
            atomicAdd(&g_seg[dhi * MD + col], (vhi[t * 2 + d] - mhi) * ihi * eng[col] + enb[col]);
        }
    }
}

// ---------------- node pre: m_i = LN(seg/cnt), z = [LN(feats)|m_i]; zeroes g_seg ----------------
__global__ void k_node_pre(int off, const float* __restrict__ eng, const float* __restrict__ enb,
                           const float* __restrict__ n1g, const float* __restrict__ n1b) {
    int node = blockIdx.x * 8 + (threadIdx.x >> 5);
    int lane = threadIdx.x & 31;
    if (node >= NN) return;

    float x = g_seg[node * MD + lane] / fmaxf(g_cnt[node], 1.f);
    g_seg[node * MD + lane] = 0.f;  // ready for next layer
    float S = x;
#pragma unroll
    for (int o = 16; o; o >>= 1) S += __shfl_xor_sync(0xffffffffu, S, o);
    float mean = S * (1.f / 32.f);
    float d = x - mean;
    float V = d * d;
#pragma unroll
    for (int o = 16; o; o >>= 1) V += __shfl_xor_sync(0xffffffffu, V, o);
    V *= (1.f / 32.f);
    g_z[node * 160 + 128 + lane] = d * rsqrtf(V + EPSF) * eng[lane] + enb[lane];

    float4 v = *(const float4*)&g_cat[node * CAT + off + lane * 4];
    S = v.x + v.y + v.z + v.w;
#pragma unroll
    for (int o = 16; o; o >>= 1) S += __shfl_xor_sync(0xffffffffu, S, o);
    mean = S * (1.f / 128.f);
    float dx = v.x - mean, dy = v.y - mean, dz = v.z - mean, dw = v.w - mean;
    V = dx * dx + dy * dy + dz * dz + dw * dw;
#pragma unroll
    for (int o = 16; o; o >>= 1) V += __shfl_xor_sync(0xffffffffu, V, o);
    V *= (1.f / 128.f);
    float inv = rsqrtf(V + EPSF);
    float4 g4 = *(const float4*)&n1g[lane * 4];
    float4 b4 = *(const float4*)&n1b[lane * 4];
    float4 o4;
    o4.x = dx * inv * g4.x + b4.x;
    o4.y = dy * inv * g4.y + b4.y;
    o4.z = dz * inv * g4.z + b4.z;
    o4.w = dw * inv * g4.w + b4.w;
    *(float4*)&g_z[node * 160 + lane * 4] = o4;
}

// ---------------- node post ----------------
__global__ void k_node_post(int off, const float* __restrict__ n2g, const float* __restrict__ n2b) {
    int node = blockIdx.x * 8 + (threadIdx.x >> 5);
    int lane = threadIdx.x & 31;
    if (node >= NN) return;
    float4 v = *(const float4*)&g_h2[node * 128 + lane * 4];
    float S = v.x + v.y + v.z + v.w;
#pragma unroll
    for (int o = 16; o; o >>= 1) S += __shfl_xor_sync(0xffffffffu, S, o);
    float mean = S * (1.f / 128.f);
    float dx = v.x - mean, dy = v.y - mean, dz = v.z - mean, dw = v.w - mean;
    float V = dx * dx + dy * dy + dz * dz + dw * dw;
#pragma unroll
    for (int o = 16; o; o >>= 1) V += __shfl_xor_sync(0xffffffffu, V, o);
    V *= (1.f / 128.f);
    float inv = rsqrtf(V + EPSF);
    float4 g4 = *(const float4*)&n2g[lane * 4];
    float4 b4 = *(const float4*)&n2b[lane * 4];
    float4 old = *(const float4*)&g_cat[node * CAT + off + lane * 4];
    float4 o4;
    o4.x = old.x + dx * inv * g4.x + b4.x;
    o4.y = old.y + dy * inv * g4.y + b4.y;
    o4.z = old.z + dz * inv * g4.z + b4.z;
    o4.w = old.w + dw * inv * g4.w + b4.w;
    *(float4*)&g_cat[node * CAT + off + 128 + lane * 4] = o4;
}

// ---------------- graph head ----------------
__global__ void k_graph(const float* __restrict__ g1W, const float* __restrict__ g1b,
                        const float* __restrict__ g2W, const float* __restrict__ g2b,
                        const float* __restrict__ g3W, const float* __restrict__ g3b,
                        float* __restrict__ out) {
    __shared__ float h[256], t[256];
    int g = blockIdx.x, tid = threadIdx.x;
    float c = fmaxf(g_pcnt[g], 1.f);
    h[tid] = g_pool[g * 256 + tid] / c;
    __syncthreads();
    float a = g1b[tid];
    for (int k = 0; k < 256; k++) a += h[k] * g1W[k * 256 + tid];
    t[tid] = silu_f(a);
    __syncthreads();
    h[tid] = t[tid];
    __syncthreads();
    a = g2b[tid];
    for (int k = 0; k < 256; k++) a += h[k] * g2W[k * 256 + tid];
    t[tid] = silu_f(a);
    __syncthreads();
    h[tid] = t[tid];
    __syncthreads();
    t[tid] = h[tid] * g3W[tid];
    __syncthreads();
    for (int s = 128; s; s >>= 1) {
        if (tid < s) t[tid] += t[tid + s];
        __syncthreads();
    }
    if (tid == 0) out[g] = t[0] + g3b[0];
}

// ---------------- launch ----------------
extern "C" void kernel_launch(void* const* d_in, const int* in_sizes, int n_in,
                              void* d_out, int out_size) {
    const int* atomids = (const int*)d_in[0];
    const float* coords = (const float*)d_in[1];
    const int* eidx = (const int*)d_in[2];
    const int* batch = (const int*)d_in[3];
    const float* emb_w = (const float*)d_in[4];
    const float* eW1 = (const float*)d_in[5];
    const float* eb1 = (const float*)d_in[6];
    const float* eW2 = (const float*)d_in[7];
    const float* eb2 = (const float*)d_in[8];
    const float* en_g = (const float*)d_in[9];
    const float* en_b = (const float*)d_in[10];
    const float* nn1_g = (const float*)d_in[11];
    const float* nn1_b = (const float*)d_in[12];
    const float* nW1 = (const float*)d_in[13];
    const float* nb1 = (const float*)d_in[14];
    const float* nW2 = (const float*)d_in[15];
    const float* nb2 = (const float*)d_in[16];
    const float* nn2_g = (const float*)d_in[17];
    const float* nn2_b = (const float*)d_in[18];
    const float* f1W = (const float*)d_in[19];
    const float* f1b = (const float*)d_in[20];
    const float* f2W = (const float*)d_in[21];
    const float* f2b = (const float*)d_in[22];
    const float* f3W = (const float*)d_in[23];
    const float* f3b = (const float*)d_in[24];
    const float* g1W = (const float*)d_in[25];
    const float* g1b = (const float*)d_in[26];
    const float* g2W = (const float*)d_in[27];
    const float* g2b = (const float*)d_in[28];
    const float* g3W = (const float*)d_in[29];
    const float* g3b = (const float*)d_in[30];
    float* out = (float*)d_out;

    // edge smem: fe(128*76) + H(128*68) + W1c(72*68) + W2c(64*36) + b1(648) + d2(128) + src/dst(256)
    const int smem_edge = (128 * 76 + 128 * 68 + 72 * 68 + 64 * 36 + 648 + 128 + 256) * 4;  // 106656
    cudaFuncSetAttribute(k_edge3, cudaFuncAttributeMaxDynamicSharedMemorySize, smem_edge);
    const int smem_gemm = (2 * 256 * 20 + 2 * 16 * 68) * 4;  // 49664
    cudaFuncSetAttribute(k_gemm3t, cudaFuncAttributeMaxDynamicSharedMemorySize, smem_gemm);

    float *pcat, *phcat, *pPa, *pPb, *pz, *ph1, *ph2, *pf1, *pf2, *pf3;
    cudaGetSymbolAddress((void**)&pcat, g_cat);
    cudaGetSymbolAddress((void**)&phcat, g_hcat);
    cudaGetSymbolAddress((void**)&pPa, g_Pa);
    cudaGetSymbolAddress((void**)&pPb, g_Pb);
    cudaGetSymbolAddress((void**)&pz, g_z);
    cudaGetSymbolAddress((void**)&ph1, g_h1);
    cudaGetSymbolAddress((void**)&ph2, g_h2);
    cudaGetSymbolAddress((void**)&pf1, g_f1);
    cudaGetSymbolAddress((void**)&pf2, g_f2);
    cudaGetSymbolAddress((void**)&pf3, g_f3);

    k_zero_start<<<(NN * MD + 255) / 256, 256>>>();
    k_deg<<<(NE + 255) / 256, 256>>>(eidx);
    k_embed<<<(NN * EMB + 255) / 256, 256>>>(atomids, emb_w);

    const int MB = (NN + 255) / 256;  // 40

    for (int k = 0; k < 5; k++) {
        int off = 128 * k;
        k_gemm3t<<<dim3(11, MB), 256, smem_gemm>>>(pcat + off, eW1 + (size_t)k * EIN * HID,
                                                   nullptr, pPa, NN, HID, EMB, CAT, HID, PLD, 0);
        k_gemm3t<<<dim3(11, MB), 256, smem_gemm>>>(pcat + off,
                                                   eW1 + (size_t)k * EIN * HID + (size_t)EMB * HID,
                                                   nullptr, pPb, NN, HID, EMB, CAT, HID, PLD, 0);
        k_edge3<<<NE / 128, 256, smem_edge>>>(eidx, coords,
                                              eW1 + (size_t)k * EIN * HID, eb1 + k * HID,
                                              eW2 + (size_t)k * HID * MD, eb2 + k * MD,
                                              en_g + k * MD, en_b + k * MD);
        k_node_pre<<<NN / 8, 256>>>(off, en_g + k * MD, en_b + k * MD,
                                    nn1_g + k * EMB, nn1_b + k * EMB);
        k_gemm3t<<<dim3(4, MB), 256, smem_gemm>>>(pz, nW1 + (size_t)k * 160 * 256, nb1 + k * 256,
                                                  ph1, NN, 256, 160, 160, 256, 256, 1);
        k_gemm3t<<<dim3(2, MB), 256, smem_gemm>>>(ph1, nW2 + (size_t)k * 256 * 128, nb2 + k * 128,
                                                  ph2, NN, 128, 256, 256, 128, 128, 0);
        k_node_post<<<NN / 8, 256>>>(off, nn2_g + k * EMB, nn2_b + k * EMB);
    }

    k_silucat<<<(NN * CAT + 255) / 256, 256>>>();
    k_gemm3t<<<dim3(4, MB), 256, smem_gemm>>>(phcat, f1W, f1b, pf1, NN, 256, CAT, CAT, 256, 256, 1);
    k_gemm3t<<<dim3(4, MB), 256, smem_gemm>>>(pf1, f2W, f2b, pf2, NN, 256, 256, 256, 256, 256, 1);
    k_gemm3t<<<dim3(4, MB), 256, smem_gemm>>>(pf2, f3W, f3b, pf3, NN, 256, 256, 256, 256, 256, 1);
    k_pool<<<(NN * 256 + 255) / 256, 256>>>(batch);
    k_graph<<<NG, 256>>>(g1W, g1b, g2W, g2b, g3W, g3b, out);
}